// round 4
// baseline (speedup 1.0000x reference)
#include <cuda_runtime.h>

#define S_LEN   2048
#define NHEADS  16
#define HD      64
#define BATCH   2
#define HID     1024

// Scratch: Q and V in head-major layout [B, H, S, 64]
__device__ float g_q[BATCH * NHEADS * S_LEN * HD];
__device__ float g_v[BATCH * NHEADS * S_LEN * HD];

// ---------------------------------------------------------------------------
// Kernel A: fused Q/V projection GEMM.
// Y = X[4096,1024] @ W[1024,1024] + b, written to head-major scratch.
// blockIdx.z selects (Wq,bq)->g_q vs (Wv,bv)->g_v.
// 128x128 tile, BK=16, 256 threads, 8x8 per thread, fp32 FFMA.
// ---------------------------------------------------------------------------
__global__ __launch_bounds__(256)
void qv_gemm(const float* __restrict__ X,
             const float* __restrict__ Wq, const float* __restrict__ bq,
             const float* __restrict__ Wv, const float* __restrict__ bv) {
    __shared__ float As[16 * 128];   // [k][m] (transposed on store)
    __shared__ float Bs[16 * 128];   // [k][n]

    const float* W    = blockIdx.z ? Wv : Wq;
    const float* bias = blockIdx.z ? bv : bq;
    float*       out  = blockIdx.z ? g_v : g_q;

    const int tid = threadIdx.x;
    const int bx = blockIdx.x, by = blockIdx.y;
    const int tx = tid & 15, ty = tid >> 4;

    const int arow = tid >> 2;            // 0..63
    const int acol = (tid & 3) << 2;      // 0,4,8,12
    const int brow = tid >> 5;            // 0..7
    const int bcol = (tid & 31) << 2;     // 0..124

    const float* Ap = X + (by * 128 + arow) * HID + acol;
    const float* Bp = W + brow * HID + bx * 128 + bcol;

    float acc[8][8];
#pragma unroll
    for (int i = 0; i < 8; i++)
#pragma unroll
        for (int j = 0; j < 8; j++) acc[i][j] = 0.0f;

    for (int k0 = 0; k0 < HID; k0 += 16) {
        float4 a0 = *(const float4*)(Ap + k0);
        float4 a1 = *(const float4*)(Ap + 64 * HID + k0);
        float4 b0 = *(const float4*)(Bp + (k0    ) * HID);
        float4 b1 = *(const float4*)(Bp + (k0 + 8) * HID);

        __syncthreads();
        As[(acol + 0) * 128 + arow] = a0.x;
        As[(acol + 1) * 128 + arow] = a0.y;
        As[(acol + 2) * 128 + arow] = a0.z;
        As[(acol + 3) * 128 + arow] = a0.w;
        As[(acol + 0) * 128 + arow + 64] = a1.x;
        As[(acol + 1) * 128 + arow + 64] = a1.y;
        As[(acol + 2) * 128 + arow + 64] = a1.z;
        As[(acol + 3) * 128 + arow + 64] = a1.w;
        *(float4*)(Bs + brow * 128 + bcol)       = b0;
        *(float4*)(Bs + (brow + 8) * 128 + bcol) = b1;
        __syncthreads();

#pragma unroll
        for (int k = 0; k < 16; k++) {
            float ar[8], br[8];
            *(float4*)(ar)     = *(const float4*)(As + k * 128 + ty * 8);
            *(float4*)(ar + 4) = *(const float4*)(As + k * 128 + ty * 8 + 4);
            *(float4*)(br)     = *(const float4*)(Bs + k * 128 + tx * 8);
            *(float4*)(br + 4) = *(const float4*)(Bs + k * 128 + tx * 8 + 4);
#pragma unroll
            for (int i = 0; i < 8; i++)
#pragma unroll
                for (int j = 0; j < 8; j++)
                    acc[i][j] += ar[i] * br[j];
        }
    }

    // Epilogue: add bias, scatter to head-major [B,H,S,64]
    const int nbase = bx * 128 + tx * 8;
    float bb[8];
#pragma unroll
    for (int j = 0; j < 8; j++) bb[j] = bias[nbase + j];
    const int hh = nbase >> 6;      // head
    const int d0 = nbase & 63;      // dim offset (multiple of 8)

#pragma unroll
    for (int i = 0; i < 8; i++) {
        int m  = by * 128 + ty * 8 + i;
        int bi = m >> 11;           // batch
        int s  = m & 2047;          // seq pos
        float* op = out + (((bi * NHEADS + hh) * S_LEN + s) * HD + d0);
        float4 r;
        r.x = acc[i][0] + bb[0]; r.y = acc[i][1] + bb[1];
        r.z = acc[i][2] + bb[2]; r.w = acc[i][3] + bb[3];
        *(float4*)(op) = r;
        r.x = acc[i][4] + bb[4]; r.y = acc[i][5] + bb[5];
        r.z = acc[i][6] + bb[6]; r.w = acc[i][7] + bb[7];
        *(float4*)(op + 4) = r;
    }
}

// ---------------------------------------------------------------------------
// Kernel B: block-sparse attention with online softmax.
// Strided-mask structure (STRIDE=128, masked logits underflow exp -> exact 0):
//   query tile t, query a (0..127), i = 128t + a:
//     - self key i                      (processed first, seeds the max)
//     - diag block t:   keys c < a      (lower triangle)
//     - prev block t-1: keys c >= a     (upper triangle, incl. c==a: diff=128)
//     - blocks m <= t-2: only key 128m + a (diagonal gather)
// Diag/prev triangles are complementary -> one fused 128-iteration loop with
// full lane utilization and warp-broadcast smem reads.
// One thread per query; scores ( /8 ) + attention_mask honored.
// ---------------------------------------------------------------------------
#define PROC_KEY(KP, VP, AMJ) do {                                            \
    float s0 = 0.f, s1 = 0.f, s2 = 0.f, s3 = 0.f;                             \
    const float4* kk4 = (const float4*)(KP);                                  \
    _Pragma("unroll")                                                         \
    for (int d4 = 0; d4 < 16; d4++) {                                         \
        float4 kk = kk4[d4];                                                  \
        s0 += q[d4*4+0] * kk.x; s1 += q[d4*4+1] * kk.y;                       \
        s2 += q[d4*4+2] * kk.z; s3 += q[d4*4+3] * kk.w;                       \
    }                                                                         \
    float s = ((s0 + s1) + (s2 + s3)) * 0.125f + (AMJ);                       \
    if (s > mx) {                                                             \
        float corr = __expf(mx - s);                                          \
        l *= corr;                                                            \
        _Pragma("unroll")                                                     \
        for (int d = 0; d < 64; d++) ctx[d] *= corr;                          \
        mx = s;                                                               \
    }                                                                         \
    float p = __expf(s - mx);                                                 \
    l += p;                                                                   \
    const float4* vv4 = (const float4*)(VP);                                  \
    _Pragma("unroll")                                                         \
    for (int d4 = 0; d4 < 16; d4++) {                                         \
        float4 vv = vv4[d4];                                                  \
        ctx[d4*4+0] += p * vv.x; ctx[d4*4+1] += p * vv.y;                     \
        ctx[d4*4+2] += p * vv.z; ctx[d4*4+3] += p * vv.w;                     \
    }                                                                         \
} while (0)

__global__ __launch_bounds__(128)
void attn_kernel(const float* __restrict__ AM, float* __restrict__ Out) {
    extern __shared__ float sm[];
    float* kd = sm;                // diag keys   [128][64]
    float* vd = sm + 8192;         // diag values
    float* kp = sm + 16384;        // prev keys
    float* vp = sm + 24576;        // prev values

    const int t = blockIdx.x, h = blockIdx.y, b = blockIdx.z;
    const int a = threadIdx.x;          // query within tile
    const int i = t * 128 + a;          // global query row

    const float* Qbh = g_q + ((b * NHEADS + h) * S_LEN) * HD;
    const float* Vbh = g_v + ((b * NHEADS + h) * S_LEN) * HD;
    const float* am  = AM + b * S_LEN;

    // Cooperative stage of diag (+ prev) K/V tiles: fully coalesced float4.
    {
        const float4* sk = (const float4*)(Qbh + t * 128 * HD);
        const float4* sv = (const float4*)(Vbh + t * 128 * HD);
        float4* dk = (float4*)kd;
        float4* dv = (float4*)vd;
#pragma unroll
        for (int it = 0; it < 16; it++) {
            int x = it * 128 + a;
            dk[x] = sk[x];
            dv[x] = sv[x];
        }
        if (t > 0) {
            const float4* sk2 = (const float4*)(Qbh + (t - 1) * 128 * HD);
            const float4* sv2 = (const float4*)(Vbh + (t - 1) * 128 * HD);
            float4* dk2 = (float4*)kp;
            float4* dv2 = (float4*)vp;
#pragma unroll
            for (int it = 0; it < 16; it++) {
                int x = it * 128 + a;
                dk2[x] = sk2[x];
                dv2[x] = sv2[x];
            }
        }
    }

    // Load q and self-v from global (avoids 32-way smem bank conflicts).
    float q[64], ctx[64];
    {
        const float4* qg = (const float4*)(Qbh + i * HD);
        const float4* vg = (const float4*)(Vbh + i * HD);
#pragma unroll
        for (int d4 = 0; d4 < 16; d4++) {
            float4 f = qg[d4];
            q[d4*4+0] = f.x; q[d4*4+1] = f.y; q[d4*4+2] = f.z; q[d4*4+3] = f.w;
            float4 g = vg[d4];
            ctx[d4*4+0] = g.x; ctx[d4*4+1] = g.y; ctx[d4*4+2] = g.z; ctx[d4*4+3] = g.w;
        }
    }

    // Self key first: seeds max high (s_ii = |q|^2/8 is typically the max),
    // making the online-softmax rescale branch rare.
    float mx, l;
    {
        float s0 = 0.f, s1 = 0.f, s2 = 0.f, s3 = 0.f;
#pragma unroll
        for (int d = 0; d < 64; d += 4) {
            s0 += q[d] * q[d];     s1 += q[d+1] * q[d+1];
            s2 += q[d+2] * q[d+2]; s3 += q[d+3] * q[d+3];
        }
        mx = ((s0 + s1) + (s2 + s3)) * 0.125f + am[i];
        l = 1.0f;                  // p_self = 1, ctx already = v_self
    }

    __syncthreads();

    // Fused diag/prev loop: lane a takes diag key c when c < a, prev key c
    // when c >= a (t > 0). Complementary -> every lane active every iter.
    for (int c = 0; c < 128; c++) {
        bool isdiag = (c < a);
        bool active = isdiag || (t > 0);
        if (active) {
            const float* kbp = isdiag ? (kd + c * HD) : (kp + c * HD);
            const float* vbp = isdiag ? (vd + c * HD) : (vp + c * HD);
            int jrow = isdiag ? (t * 128 + c) : ((t - 1) * 128 + c);
            PROC_KEY(kbp, vbp, am[jrow]);
        }
    }

    // Strided keys: one per earlier block, row 128*m + a (per-thread gather).
    for (int mm = 0; mm + 1 < t; mm++) {
        int r = mm * 128 + a;
        PROC_KEY(Qbh + r * HD, Vbh + r * HD, am[r]);
    }

    // Normalize and write out[b, i, h*64 + d]
    float inv = 1.0f / l;
    float4* og = (float4*)(Out + (b * S_LEN + i) * (NHEADS * HD) + h * HD);
#pragma unroll
    for (int d4 = 0; d4 < 16; d4++) {
        float4 o;
        o.x = ctx[d4*4+0] * inv; o.y = ctx[d4*4+1] * inv;
        o.z = ctx[d4*4+2] * inv; o.w = ctx[d4*4+3] * inv;
        og[d4] = o;
    }
}

// ---------------------------------------------------------------------------
extern "C" void kernel_launch(void* const* d_in, const int* in_sizes, int n_in,
                              void* d_out, int out_size) {
    const float* X  = (const float*)d_in[0];
    const float* AM = (const float*)d_in[1];
    const float* Wq = (const float*)d_in[2];
    const float* bq = (const float*)d_in[3];
    const float* Wv = (const float*)d_in[4];
    const float* bv = (const float*)d_in[5];
    float* out = (float*)d_out;

    cudaFuncSetAttribute(attn_kernel,
                         cudaFuncAttributeMaxDynamicSharedMemorySize, 131072);

    qv_gemm<<<dim3(8, 32, 2), 256>>>(X, Wq, bq, Wv, bv);
    attn_kernel<<<dim3(16, NHEADS, BATCH), 128, 131072>>>(AM, out);
}